// round 1
// baseline (speedup 1.0000x reference)
#include <cuda_runtime.h>
#include <math_constants.h>

// SpatialArgmax2d: per (B,N) 128x128 heatmap, argmax + sub-pixel parabolic fit.
// Input:  (B, N, H, W) fp32, B*N = 2048 maps of 16384 floats (64 KB each).
// Output: (B, N, 2) fp32 -> (x + dx, y + dy).
//
// One CTA per map. 256 threads x 16 float4 loads each = 16384 elements,
// fully coalesced. Block argmax with first-index tie-break, then thread 0
// does the 5-point stencil (clamped indices == replicate edge pad) and the
// quadratic refinement.

#define HH 128
#define WW 128
#define TPB 256
#define ELEMS_PER_MAP (HH * WW)          // 16384
#define VEC4_PER_MAP (ELEMS_PER_MAP / 4) // 4096
#define VEC4_PER_THREAD (VEC4_PER_MAP / TPB) // 16

__global__ __launch_bounds__(TPB) void spatial_argmax2d_kernel(
    const float* __restrict__ in, float* __restrict__ out)
{
    const int map = blockIdx.x;
    const float* __restrict__ m = in + (size_t)map * ELEMS_PER_MAP;
    const float4* __restrict__ m4 = reinterpret_cast<const float4*>(m);
    const int tid = threadIdx.x;

    float best = -CUDART_INF_F;
    int bestIdx = 0;

    // Coalesced strided float4 loads. Indices within a thread are strictly
    // increasing, so a strict '>' keeps the first (lowest-index) maximum.
    #pragma unroll
    for (int k = 0; k < VEC4_PER_THREAD; ++k) {
        const int i4 = tid + k * TPB;
        const float4 v = m4[i4];
        const int base = i4 << 2;
        if (v.x > best) { best = v.x; bestIdx = base + 0; }
        if (v.y > best) { best = v.y; bestIdx = base + 1; }
        if (v.z > best) { best = v.z; bestIdx = base + 2; }
        if (v.w > best) { best = v.w; bestIdx = base + 3; }
    }

    // Warp reduction with first-index tie-break.
    #pragma unroll
    for (int off = 16; off > 0; off >>= 1) {
        const float ov = __shfl_down_sync(0xffffffffu, best, off);
        const int   oi = __shfl_down_sync(0xffffffffu, bestIdx, off);
        if (ov > best || (ov == best && oi < bestIdx)) { best = ov; bestIdx = oi; }
    }

    __shared__ float sval[TPB / 32];
    __shared__ int   sidx[TPB / 32];
    const int lane = tid & 31;
    const int warp = tid >> 5;
    if (lane == 0) { sval[warp] = best; sidx[warp] = bestIdx; }
    __syncthreads();

    if (tid == 0) {
        best = sval[0]; bestIdx = sidx[0];
        #pragma unroll
        for (int w = 1; w < TPB / 32; ++w) {
            const float ov = sval[w];
            const int   oi = sidx[w];
            if (ov > best || (ov == best && oi < bestIdx)) { best = ov; bestIdx = oi; }
        }

        const int y = bestIdx / WW;
        const int x = bestIdx - y * WW;

        // 5-point stencil with clamped indices == replicate ('edge') padding.
        const int xl = x > 0        ? x - 1 : 0;
        const int xr = x < WW - 1   ? x + 1 : WW - 1;
        const int yu = y > 0        ? y - 1 : 0;
        const int yd = y < HH - 1   ? y + 1 : HH - 1;

        const float c = best;
        const float l = m[y  * WW + xl];
        const float r = m[y  * WW + xr];
        const float u = m[yu * WW + x ];
        const float d = m[yd * WW + x ];

        const float den_x = l - 2.0f * c + r;
        const float den_y = u - 2.0f * c + d;
        const float dx = (den_x != 0.0f) ? 0.5f * (l - r) / den_x : 0.0f;
        const float dy = (den_y != 0.0f) ? 0.5f * (u - d) / den_y : 0.0f;

        out[map * 2 + 0] = (float)x + dx;
        out[map * 2 + 1] = (float)y + dy;
    }
}

extern "C" void kernel_launch(void* const* d_in, const int* in_sizes, int n_in,
                              void* d_out, int out_size)
{
    const float* in = (const float*)d_in[0];
    float* out = (float*)d_out;
    const int maps = in_sizes[0] / ELEMS_PER_MAP; // B*N = 2048
    spatial_argmax2d_kernel<<<maps, TPB>>>(in, out);
}